// round 12
// baseline (speedup 1.0000x reference)
#include <cuda_runtime.h>
#include <cuda_bf16.h>

#define Bb   8
#define T    16
#define C    64
#define Hh   56
#define Ww   56
#define HW   3136          // 56*56
#define HW4  784           // HW/4
#define DIN  64            // 8*8 pooled
#define DOUT 32            // 2*d_t
#define NBC  512           // b*c
#define NTHR 512           // threads per block

// dynamic smem layout (floats):
//   sx   [16][3136]   50176   x tile for this n
//   sW   [2][2048]     4096   Wq, Wk
//   flat [16][64]      1024
//   sq   [16][33]       528
//   sk   [16][33]       528
//   satt [256]          256
// total 56608 floats = 226432 bytes
#define SMEM_BYTES 226432

#define OFF_SX   0
#define OFF_W    50176
#define OFF_FLAT 54272
#define OFF_Q    55296
#define OFF_K    55824
#define OFF_ATT  56352

__global__ __launch_bounds__(NTHR, 1)
void fused_kernel(const float* __restrict__ x, float* __restrict__ out,
                  const float* __restrict__ Wq, const float* __restrict__ bq,
                  const float* __restrict__ Wk, const float* __restrict__ bk)
{
    extern __shared__ float smem[];
    float* sx   = smem + OFF_SX;
    float* sW   = smem + OFF_W;          // [0:2048)=Wq, [2048:4096)=Wk
    float* flat = smem + OFF_FLAT;       // [t][64]
    float* sq   = smem + OFF_Q;          // [t][33]
    float* sk   = smem + OFF_K;          // [t][33]
    float* satt = smem + OFF_ATT;        // [t*16+s]

    const int n   = blockIdx.x;          // n = b*C + c
    const int b   = n >> 6;
    const int c   = n & 63;
    const int tid = threadIdx.x;

    // ---- Phase 1: stage weights + the full x[b,:,c,:] tile (200 KB) ----
    for (int i = tid; i < 2 * DIN * DOUT; i += NTHR)
        sW[i] = (i < DIN * DOUT) ? Wq[i] : Wk[i - DIN * DOUT];

    {
        const float4* xg = (const float4*)x + ((size_t)b * T * C + c) * HW4;
        float4* sx4 = (float4*)sx;
        #pragma unroll 4
        for (int i = tid; i < T * HW4; i += NTHR) {
            const int s = i / HW4;
            const int p = i - s * HW4;
            sx4[i] = xg[(size_t)s * (C * HW4) + p];
        }
    }
    __syncthreads();

    // ---- Phase 2: pool 16 x (56x56 -> 8x8), 1024 bins, 2 per thread ----
    #pragma unroll
    for (int bi = tid; bi < T * DIN; bi += NTHR) {
        const int t   = bi >> 6;
        const int bin = bi & 63;
        const int d1 = bin >> 3, d2 = bin & 7;
        const float* base = sx + t * HW + (7 * d1) * Ww + 7 * d2;
        float a0 = 0.f, a1 = 0.f, a2 = 0.f, a3 = 0.f;
        #pragma unroll
        for (int dh = 0; dh < 7; ++dh) {
            const float* row = base + dh * Ww;
            a0 += row[0];
            a1 += row[1];
            a2 += row[2];
            a3 += row[3];
            a0 += row[4];
            a1 += row[5];
            a2 += row[6];
        }
        flat[t * DIN + bin] = (a0 + a1 + a2 + a3) * (1.f / 49.f);
    }
    __syncthreads();

    // ---- Phase 3: q = flat@Wq + bq ; k = flat@Wk + bk (1 col pair/thread) --
    {
        const int tt = tid >> 5, j = tid & 31;   // tid < 512 = 16*32
        float aq = bq[j];
        float ak = bk[j];
        const float* f = flat + tt * DIN;
        #pragma unroll
        for (int d = 0; d < DIN; ++d) {
            aq = fmaf(f[d], sW[d * DOUT + j], aq);
            ak = fmaf(f[d], sW[DIN * DOUT + d * DOUT + j], ak);
        }
        sq[tt * 33 + j] = aq;
        sk[tt * 33 + j] = ak;
    }
    __syncthreads();

    // ---- Phase 4: logits + shuffle softmax (threads 0..255) ----
    if (tid < 256) {
        const int i = tid >> 4, j = tid & 15;
        float s = 0.f;
        #pragma unroll
        for (int d = 0; d < DOUT; ++d)
            s = fmaf(sq[i * 33 + d], sk[j * 33 + d], s);
        s *= 0.25f;                              // 1/sqrt(16)
        float mx = s;
        #pragma unroll
        for (int k = 8; k >= 1; k >>= 1)
            mx = fmaxf(mx, __shfl_xor_sync(0xffffffffu, mx, k));
        float e = __expf(s - mx);
        float ssum = e;
        #pragma unroll
        for (int k = 8; k >= 1; k >>= 1)
            ssum += __shfl_xor_sync(0xffffffffu, ssum, k);
        satt[tid] = e * (1.f / ssum);
    }
    __syncthreads();

    // ---- Phase 5: av from smem: out[t][col] = sum_s att[t][s]*sx[s][col] ----
    {
        const float4* sx4 = (const float4*)sx;
        float4* og = (float4*)out + ((size_t)b * T * C + c) * HW4;

        for (int col = tid; col < HW4; col += NTHR) {
            float4 v[T];
            #pragma unroll
            for (int s = 0; s < T; ++s)
                v[s] = sx4[s * HW4 + col];

            #pragma unroll
            for (int t = 0; t < T; ++t) {
                float4 a = make_float4(0.f, 0.f, 0.f, 0.f);
                #pragma unroll
                for (int s = 0; s < T; ++s) {
                    const float w = satt[t * T + s];
                    a.x = fmaf(w, v[s].x, a.x);
                    a.y = fmaf(w, v[s].y, a.y);
                    a.z = fmaf(w, v[s].z, a.z);
                    a.w = fmaf(w, v[s].w, a.w);
                }
                __stcs(&og[(size_t)t * (C * HW4) + col], a);
            }
        }
    }
}

// ---------------------------------------------------------------------------
extern "C" void kernel_launch(void* const* d_in, const int* in_sizes, int n_in,
                              void* d_out, int out_size)
{
    const float* x  = (const float*)d_in[0];
    const float* Wq = (const float*)d_in[1];
    const float* bq = (const float*)d_in[2];
    const float* Wk = (const float*)d_in[3];
    const float* bk = (const float*)d_in[4];
    float* out = (float*)d_out;

    cudaFuncSetAttribute(fused_kernel,
                         cudaFuncAttributeMaxDynamicSharedMemorySize,
                         SMEM_BYTES);
    fused_kernel<<<NBC, NTHR, SMEM_BYTES>>>(x, out, Wq, bq, Wk, bk);
}

// round 13
// speedup vs baseline: 1.2051x; 1.2051x over previous
#include <cuda_runtime.h>
#include <cuda_bf16.h>

#define Bb   8
#define T    16
#define C    64
#define Hh   56
#define Ww   56
#define HW   3136          // 56*56
#define HW4  784           // HW/4
#define DIN  64            // 8*8 pooled
#define DOUT 32            // 2*d_t
#define NBC  512           // b*c
#define NT   (NBC * T)     // 8192 (n,t) slices
#define NCOL (NBC * HW4)   // 401408 float4 columns (= 1568 * 256)

// scratch
__device__ float g_flat[NT * DIN];       // pooled features [n*T+t][64], 2MB
__device__ float g_att[NBC * T * T];     // softmaxed attention, 512KB

// ---------------------------------------------------------------------------
// Kernel 1: pooling, warp-autonomous. One block per (n,t) slice; each warp
// owns one bin-row (7 image rows x 56 cols). ~5.5 TB/s = read ceiling.
// ---------------------------------------------------------------------------
__global__ __launch_bounds__(256)
void pool_kernel(const float* __restrict__ x)
{
    const int nt   = blockIdx.x;        // n*T + t
    const int n    = nt >> 4;
    const int t    = nt & 15;
    const int b    = n >> 6;
    const int c    = n & 63;
    const int wid  = threadIdx.x >> 5;  // d1 = bin row, 0..7
    const int lane = threadIdx.x & 31;

    __shared__ float scol[8][56 + 8];   // per-warp column sums (padded)

    const float* slice = x + ((size_t)(b * T + t) * C + c) * HW;
    const float2* rows = (const float2*)(slice + (7 * wid) * Ww);  // 28 f2/row

    if (lane < 28) {
        float2 s = make_float2(0.f, 0.f);
        #pragma unroll
        for (int dh = 0; dh < 7; ++dh) {
            const float2 v = rows[dh * (Ww / 2) + lane];
            s.x += v.x;
            s.y += v.y;
        }
        scol[wid][2 * lane]     = s.x;
        scol[wid][2 * lane + 1] = s.y;
    }
    __syncwarp();

    if (lane < 8) {
        const float* cs = &scol[wid][7 * lane];
        float a0 = cs[0] + cs[1];
        float a1 = cs[2] + cs[3];
        float a2 = cs[4] + cs[5];
        a0 += cs[6];
        g_flat[nt * DIN + wid * 8 + lane] = (a0 + a1 + a2) * (1.f / 49.f);
    }
}

// ---------------------------------------------------------------------------
// Kernel 2: q/k projection + att + register/shuffle softmax. One block per n.
// PDL: weights staged pre-sync; g_flat read post-sync.
// ---------------------------------------------------------------------------
__global__ __launch_bounds__(256)
void att_kernel(const float* __restrict__ Wq, const float* __restrict__ bq,
                const float* __restrict__ Wk, const float* __restrict__ bk)
{
    const int n   = blockIdx.x;
    const int tid = threadIdx.x;

    __shared__ float flat[T][DIN];           // 4 KB
    __shared__ float sWq[DIN * DOUT];        // 8 KB
    __shared__ float sWk[DIN * DOUT];        // 8 KB
    __shared__ float sq[T][DOUT + 1];
    __shared__ float sk[T][DOUT + 1];

    // pre-sync: pure-input staging (independent of pool's output)
    for (int i = tid; i < DIN * DOUT; i += 256) {
        sWq[i] = Wq[i];
        sWk[i] = Wk[i];
    }

    cudaGridDependencySynchronize();         // wait for pool's g_flat

    for (int i = tid; i < T * DIN; i += 256)
        ((float*)flat)[i] = g_flat[n * T * DIN + i];
    __syncthreads();

    for (int i = tid; i < T * DOUT; i += 256) {
        const int tt = i >> 5, j = i & 31;
        float aq = bq[j];
        float ak = bk[j];
        #pragma unroll
        for (int d = 0; d < DIN; ++d) {
            const float f = flat[tt][d];
            aq = fmaf(f, sWq[d * DOUT + j], aq);
            ak = fmaf(f, sWk[d * DOUT + j], ak);
        }
        sq[tt][j] = aq;
        sk[tt][j] = ak;
    }
    __syncthreads();

    const int i = tid >> 4, j = tid & 15;
    float s = 0.f;
    #pragma unroll
    for (int d = 0; d < DOUT; ++d)
        s = fmaf(sq[i][d], sk[j][d], s);
    s *= 0.25f;                          // 1/sqrt(16)

    float m = s;
    #pragma unroll
    for (int k = 8; k >= 1; k >>= 1)
        m = fmaxf(m, __shfl_xor_sync(0xffffffffu, m, k));
    float e = __expf(s - m);
    float ssum = e;
    #pragma unroll
    for (int k = 8; k >= 1; k >>= 1)
        ssum += __shfl_xor_sync(0xffffffffu, ssum, k);

    g_att[n * (T * T) + tid] = e * (1.f / ssum);
}

// ---------------------------------------------------------------------------
// Kernel 3: out[b,t,c,:] = sum_s att[n,t,s] * x[b,s,c,:]
// __launch_bounds__(256,3): cap regs at 85 -> 3 CTAs/SM (occupancy +50% vs 2).
// PDL: the 16 x-loads issued PRE-sync. Reversed n order for L2 reuse of x;
// __stcs streaming stores.
// ---------------------------------------------------------------------------
__global__ __launch_bounds__(256, 3)
void av_kernel(const float* __restrict__ x, float* __restrict__ out)
{
    const int tid  = threadIdx.x;
    const int gid0 = blockIdx.x << 8;               // first column of block
    const int n0   = gid0 / HW4;                    // block spans n0 or n0+1

    const int gid = gid0 + tid;
    const int n   = gid / HW4;
    const int p4  = gid - n * HW4;
    const int m   = n - n0;
    const int rn  = NBC - 1 - n;                    // reversed n
    const int b   = rn >> 6;
    const int c   = rn & 63;

    const int stride_s = C * HW4;                   // float4 stride per t/s
    const int base     = (b * T * C + c) * HW4 + p4;
    const float4* xb = (const float4*)x + base;
    float4* ob = (float4*)out + base;

    // pre-sync: issue the 16 strided x loads (no dependency on att)
    float4 v[T];
    #pragma unroll
    for (int s = 0; s < T; ++s)
        v[s] = xb[s * stride_s];

    cudaGridDependencySynchronize();                // wait for att's g_att

    // stage att rows for the (at most) 2 reversed-n's this block touches
    __shared__ float satt[2][T * T];
    #pragma unroll
    for (int i = tid; i < 2 * T * T; i += 256) {
        const int mm  = i >> 8;
        const int idx = i & 255;
        const int nn  = n0 + mm;
        satt[mm][idx] = (nn < NBC) ? g_att[(NBC - 1 - nn) * (T * T) + idx] : 0.f;
    }
    __syncthreads();

    const float* arow = satt[m];
    #pragma unroll
    for (int t = 0; t < T; ++t) {
        float4 a = make_float4(0.f, 0.f, 0.f, 0.f);
        #pragma unroll
        for (int s = 0; s < T; ++s) {
            const float w = arow[t * T + s];
            a.x = fmaf(w, v[s].x, a.x);
            a.y = fmaf(w, v[s].y, a.y);
            a.z = fmaf(w, v[s].z, a.z);
            a.w = fmaf(w, v[s].w, a.w);
        }
        __stcs(&ob[t * stride_s], a);               // streaming store
    }
}

// ---------------------------------------------------------------------------
extern "C" void kernel_launch(void* const* d_in, const int* in_sizes, int n_in,
                              void* d_out, int out_size)
{
    const float* x  = (const float*)d_in[0];
    const float* Wq = (const float*)d_in[1];
    const float* bq = (const float*)d_in[2];
    const float* Wk = (const float*)d_in[3];
    const float* bk = (const float*)d_in[4];
    float* out = (float*)d_out;

    pool_kernel<<<NT, 256>>>(x);

    cudaLaunchAttribute attr[1];
    attr[0].id = cudaLaunchAttributeProgrammaticStreamSerialization;
    attr[0].val.programmaticStreamSerializationAllowed = 1;

    {
        cudaLaunchConfig_t cfg = {};
        cfg.gridDim  = dim3(NBC);
        cfg.blockDim = dim3(256);
        cfg.dynamicSmemBytes = 0;
        cfg.stream = 0;
        cfg.attrs = attr;
        cfg.numAttrs = 1;
        cudaLaunchKernelEx(&cfg, att_kernel, Wq, bq, Wk, bk);
    }
    {
        cudaLaunchConfig_t cfg = {};
        cfg.gridDim  = dim3(NCOL / 256);
        cfg.blockDim = dim3(256);
        cfg.dynamicSmemBytes = 0;
        cfg.stream = 0;
        cfg.attrs = attr;
        cfg.numAttrs = 1;
        cudaLaunchKernelEx(&cfg, av_kernel, x, out);
    }
}

// round 14
// speedup vs baseline: 1.3003x; 1.0790x over previous
#include <cuda_runtime.h>
#include <cuda_bf16.h>

#define Bb   8
#define T    16
#define C    64
#define Hh   56
#define Ww   56
#define HW   3136          // 56*56
#define HW4  784           // HW/4
#define DIN  64            // 8*8 pooled
#define DOUT 32            // 2*d_t
#define NBC  512           // b*c
#define NCOL (NBC * HW4)   // 401408 float4 columns (= 1568 * 256)

// scratch: softmaxed attention [n][t][s], 512KB
__device__ float g_att[NBC * T * T];

// ---------------------------------------------------------------------------
// Kernel 1 (fused pool+att): one block per n = (b,c), 512 threads / 16 warps.
// Warp w pools slice t=w (56x56 -> 8x8; same LDG.64 pattern & aggregate MLP
// as the proven split pool). Then q/k projection + logits + shuffle softmax
// entirely from smem, writing g_att. No g_flat roundtrip, no att kernel.
// ---------------------------------------------------------------------------
__global__ __launch_bounds__(512)
void pool_att_kernel(const float* __restrict__ x,
                     const float* __restrict__ Wq, const float* __restrict__ bq,
                     const float* __restrict__ Wk, const float* __restrict__ bk)
{
    const int n    = blockIdx.x;        // n = b*C + c
    const int b    = n >> 6;
    const int c    = n & 63;
    const int tid  = threadIdx.x;
    const int wid  = tid >> 5;          // t slice, 0..15
    const int lane = tid & 31;

    __shared__ float scol[16][64];           // per-warp column sums
    __shared__ float flat[T][DIN];           // pooled features
    __shared__ float sWq[DIN * DOUT];        // 8 KB
    __shared__ float sWk[DIN * DOUT];        // 8 KB
    __shared__ float sq[T][DOUT + 1];
    __shared__ float sk[T][DOUT + 1];

    // stage weights (overlaps with the x loads below across warps)
    for (int i = tid; i < DIN * DOUT; i += 512) {
        sWq[i] = Wq[i];
        sWk[i] = Wk[i];
    }

    // ---- pool: warp wid owns slice t=wid; iterate the 8 bin-rows ----
    const float* slice = x + ((size_t)(b * T + wid) * C + c) * HW;
    #pragma unroll
    for (int d1 = 0; d1 < 8; ++d1) {
        if (lane < 28) {
            const float2* rows = (const float2*)(slice + (7 * d1) * Ww);
            float2 s = make_float2(0.f, 0.f);
            #pragma unroll
            for (int dh = 0; dh < 7; ++dh) {
                const float2 v = rows[dh * (Ww / 2) + lane];
                s.x += v.x;
                s.y += v.y;
            }
            scol[wid][2 * lane]     = s.x;
            scol[wid][2 * lane + 1] = s.y;
        }
        __syncwarp();
        if (lane < 8) {
            const float* cs = &scol[wid][7 * lane];
            float a0 = cs[0] + cs[1];
            float a1 = cs[2] + cs[3];
            float a2 = cs[4] + cs[5];
            a0 += cs[6];
            flat[wid][d1 * 8 + lane] = (a0 + a1 + a2) * (1.f / 49.f);
        }
        __syncwarp();
    }
    __syncthreads();

    // ---- q = flat@Wq + bq ; k = flat@Wk + bk (one (t,j) pair per thread) --
    {
        const int tt = tid >> 5, j = tid & 31;   // 16*32 = 512 ✓
        float aq = bq[j];
        float ak = bk[j];
        #pragma unroll
        for (int d = 0; d < DIN; ++d) {
            const float f = flat[tt][d];
            aq = fmaf(f, sWq[d * DOUT + j], aq);
            ak = fmaf(f, sWk[d * DOUT + j], ak);
        }
        sq[tt][j] = aq;
        sk[tt][j] = ak;
    }
    __syncthreads();

    // ---- logits + shuffle softmax (threads 0..255) ----
    if (tid < 256) {
        const int i = tid >> 4, j = tid & 15;
        float s = 0.f;
        #pragma unroll
        for (int d = 0; d < DOUT; ++d)
            s = fmaf(sq[i][d], sk[j][d], s);
        s *= 0.25f;                          // 1/sqrt(16)

        float m = s;
        #pragma unroll
        for (int k = 8; k >= 1; k >>= 1)
            m = fmaxf(m, __shfl_xor_sync(0xffffffffu, m, k));
        float e = __expf(s - m);
        float ssum = e;
        #pragma unroll
        for (int k = 8; k >= 1; k >>= 1)
            ssum += __shfl_xor_sync(0xffffffffu, ssum, k);

        g_att[n * (T * T) + tid] = e * (1.f / ssum);
    }
}

// ---------------------------------------------------------------------------
// Kernel 2: out[b,t,c,:] = sum_s att[n,t,s] * x[b,s,c,:]
// Identical to R13 winner: __launch_bounds__(256,3) (3 CTAs/SM), PDL pre-sync
// x loads, reversed-n for L2 reuse, __stcs streaming stores.
// ---------------------------------------------------------------------------
__global__ __launch_bounds__(256, 3)
void av_kernel(const float* __restrict__ x, float* __restrict__ out)
{
    const int tid  = threadIdx.x;
    const int gid0 = blockIdx.x << 8;               // first column of block
    const int n0   = gid0 / HW4;                    // block spans n0 or n0+1

    const int gid = gid0 + tid;
    const int n   = gid / HW4;
    const int p4  = gid - n * HW4;
    const int m   = n - n0;
    const int rn  = NBC - 1 - n;                    // reversed n
    const int b   = rn >> 6;
    const int c   = rn & 63;

    const int stride_s = C * HW4;                   // float4 stride per t/s
    const int base     = (b * T * C + c) * HW4 + p4;
    const float4* xb = (const float4*)x + base;
    float4* ob = (float4*)out + base;

    // pre-sync: issue the 16 strided x loads (no dependency on att)
    float4 v[T];
    #pragma unroll
    for (int s = 0; s < T; ++s)
        v[s] = xb[s * stride_s];

    cudaGridDependencySynchronize();                // wait for g_att

    // stage att rows for the (at most) 2 reversed-n's this block touches
    __shared__ float satt[2][T * T];
    #pragma unroll
    for (int i = tid; i < 2 * T * T; i += 256) {
        const int mm  = i >> 8;
        const int idx = i & 255;
        const int nn  = n0 + mm;
        satt[mm][idx] = (nn < NBC) ? g_att[(NBC - 1 - nn) * (T * T) + idx] : 0.f;
    }
    __syncthreads();

    const float* arow = satt[m];
    #pragma unroll
    for (int t = 0; t < T; ++t) {
        float4 a = make_float4(0.f, 0.f, 0.f, 0.f);
        #pragma unroll
        for (int s = 0; s < T; ++s) {
            const float w = arow[t * T + s];
            a.x = fmaf(w, v[s].x, a.x);
            a.y = fmaf(w, v[s].y, a.y);
            a.z = fmaf(w, v[s].z, a.z);
            a.w = fmaf(w, v[s].w, a.w);
        }
        __stcs(&ob[t * stride_s], a);               // streaming store
    }
}

// ---------------------------------------------------------------------------
extern "C" void kernel_launch(void* const* d_in, const int* in_sizes, int n_in,
                              void* d_out, int out_size)
{
    const float* x  = (const float*)d_in[0];
    const float* Wq = (const float*)d_in[1];
    const float* bq = (const float*)d_in[2];
    const float* Wk = (const float*)d_in[3];
    const float* bk = (const float*)d_in[4];
    float* out = (float*)d_out;

    pool_att_kernel<<<NBC, 512>>>(x, Wq, bq, Wk, bk);

    cudaLaunchAttribute attr[1];
    attr[0].id = cudaLaunchAttributeProgrammaticStreamSerialization;
    attr[0].val.programmaticStreamSerializationAllowed = 1;

    cudaLaunchConfig_t cfg = {};
    cfg.gridDim  = dim3(NCOL / 256);
    cfg.blockDim = dim3(256);
    cfg.dynamicSmemBytes = 0;
    cfg.stream = 0;
    cfg.attrs = attr;
    cfg.numAttrs = 1;
    cudaLaunchKernelEx(&cfg, av_kernel, x, out);
}

// round 15
// speedup vs baseline: 1.3365x; 1.0278x over previous
#include <cuda_runtime.h>
#include <cuda_bf16.h>

#define Bb   8
#define T    16
#define C    64
#define Hh   56
#define Ww   56
#define HW   3136          // 56*56
#define HW4  784           // HW/4
#define DIN  64            // 8*8 pooled
#define DOUT 32            // 2*d_t
#define NBC  512           // b*c
#define NCOL (NBC * HW4)   // 401408 float4 columns (= 1568 * 256)

// scratch: softmaxed attention [n][t][s], 512KB
__device__ float g_att[NBC * T * T];

// ---------------------------------------------------------------------------
// Kernel 1 (fused pool+att): one block per n = (b,c), 1024 threads / 32 warps.
// TWO warps per t-slice (each owns 4 bin-rows -> only 4 serial DRAM rounds
// per warp, 2x the warp parallelism of the R14 version). Then q/k projection
// + logits + shuffle softmax entirely from smem, writing g_att.
// ---------------------------------------------------------------------------
__global__ __launch_bounds__(1024)
void pool_att_kernel(const float* __restrict__ x,
                     const float* __restrict__ Wq, const float* __restrict__ bq,
                     const float* __restrict__ Wk, const float* __restrict__ bk)
{
    const int n    = blockIdx.x;        // n = b*C + c
    const int b    = n >> 6;
    const int c    = n & 63;
    const int tid  = threadIdx.x;
    const int w    = tid >> 5;          // warp 0..31
    const int t    = w >> 1;            // slice 0..15
    const int half = w & 1;             // which 4 bin-rows
    const int lane = tid & 31;

    __shared__ float scol[32][64];           // per-warp column sums, 8 KB
    __shared__ float flat[T][DIN];           // pooled features
    __shared__ float sWq[DIN * DOUT];        // 8 KB
    __shared__ float sWk[DIN * DOUT];        // 8 KB
    __shared__ float sq[T][DOUT + 1];
    __shared__ float sk[T][DOUT + 1];

    // stage weights (overlaps with the x loads below across warps)
    for (int i = tid; i < DIN * DOUT; i += 1024) {
        sWq[i] = Wq[i];
        sWk[i] = Wk[i];
    }

    // ---- pool: warp (t,half) owns bin-rows d1 = half*4 .. half*4+3 ----
    const float* slice = x + ((size_t)(b * T + t) * C + c) * HW;
    #pragma unroll
    for (int r = 0; r < 4; ++r) {
        const int d1 = half * 4 + r;
        if (lane < 28) {
            const float2* rows = (const float2*)(slice + (7 * d1) * Ww);
            float2 s = make_float2(0.f, 0.f);
            #pragma unroll
            for (int dh = 0; dh < 7; ++dh) {
                const float2 v = rows[dh * (Ww / 2) + lane];
                s.x += v.x;
                s.y += v.y;
            }
            scol[w][2 * lane]     = s.x;
            scol[w][2 * lane + 1] = s.y;
        }
        __syncwarp();
        if (lane < 8) {
            const float* cs = &scol[w][7 * lane];
            float a0 = cs[0] + cs[1];
            float a1 = cs[2] + cs[3];
            float a2 = cs[4] + cs[5];
            a0 += cs[6];
            flat[t][d1 * 8 + lane] = (a0 + a1 + a2) * (1.f / 49.f);
        }
        __syncwarp();
    }
    __syncthreads();

    // ---- q = flat@Wq + bq ; k = flat@Wk + bk (threads 0..511) ----
    if (tid < 512) {
        const int tt = tid >> 5, j = tid & 31;
        float aq = bq[j];
        float ak = bk[j];
        #pragma unroll
        for (int d = 0; d < DIN; ++d) {
            const float f = flat[tt][d];
            aq = fmaf(f, sWq[d * DOUT + j], aq);
            ak = fmaf(f, sWk[d * DOUT + j], ak);
        }
        sq[tt][j] = aq;
        sk[tt][j] = ak;
    }
    __syncthreads();

    // ---- logits + shuffle softmax (threads 0..255) ----
    if (tid < 256) {
        const int i = tid >> 4, j = tid & 15;
        float s = 0.f;
        #pragma unroll
        for (int d = 0; d < DOUT; ++d)
            s = fmaf(sq[i][d], sk[j][d], s);
        s *= 0.25f;                          // 1/sqrt(16)

        float m = s;
        #pragma unroll
        for (int k = 8; k >= 1; k >>= 1)
            m = fmaxf(m, __shfl_xor_sync(0xffffffffu, m, k));
        float e = __expf(s - m);
        float ssum = e;
        #pragma unroll
        for (int k = 8; k >= 1; k >>= 1)
            ssum += __shfl_xor_sync(0xffffffffu, ssum, k);

        g_att[n * (T * T) + tid] = e * (1.f / ssum);
    }
}

// ---------------------------------------------------------------------------
// Kernel 2: out[b,t,c,:] = sum_s att[n,t,s] * x[b,s,c,:]
// R14 winner unchanged: __launch_bounds__(256,3), PDL pre-sync x loads,
// reversed-n for L2 reuse, __stcs streaming stores.
// ---------------------------------------------------------------------------
__global__ __launch_bounds__(256, 3)
void av_kernel(const float* __restrict__ x, float* __restrict__ out)
{
    const int tid  = threadIdx.x;
    const int gid0 = blockIdx.x << 8;               // first column of block
    const int n0   = gid0 / HW4;                    // block spans n0 or n0+1

    const int gid = gid0 + tid;
    const int n   = gid / HW4;
    const int p4  = gid - n * HW4;
    const int m   = n - n0;
    const int rn  = NBC - 1 - n;                    // reversed n
    const int b   = rn >> 6;
    const int c   = rn & 63;

    const int stride_s = C * HW4;                   // float4 stride per t/s
    const int base     = (b * T * C + c) * HW4 + p4;
    const float4* xb = (const float4*)x + base;
    float4* ob = (float4*)out + base;

    // pre-sync: issue the 16 strided x loads (no dependency on att)
    float4 v[T];
    #pragma unroll
    for (int s = 0; s < T; ++s)
        v[s] = xb[s * stride_s];

    cudaGridDependencySynchronize();                // wait for g_att

    // stage att rows for the (at most) 2 reversed-n's this block touches
    __shared__ float satt[2][T * T];
    #pragma unroll
    for (int i = tid; i < 2 * T * T; i += 256) {
        const int mm  = i >> 8;
        const int idx = i & 255;
        const int nn  = n0 + mm;
        satt[mm][idx] = (nn < NBC) ? g_att[(NBC - 1 - nn) * (T * T) + idx] : 0.f;
    }
    __syncthreads();

    const float* arow = satt[m];
    #pragma unroll
    for (int t = 0; t < T; ++t) {
        float4 a = make_float4(0.f, 0.f, 0.f, 0.f);
        #pragma unroll
        for (int s = 0; s < T; ++s) {
            const float w = arow[t * T + s];
            a.x = fmaf(w, v[s].x, a.x);
            a.y = fmaf(w, v[s].y, a.y);
            a.z = fmaf(w, v[s].z, a.z);
            a.w = fmaf(w, v[s].w, a.w);
        }
        __stcs(&ob[t * stride_s], a);               // streaming store
    }
}

// ---------------------------------------------------------------------------
extern "C" void kernel_launch(void* const* d_in, const int* in_sizes, int n_in,
                              void* d_out, int out_size)
{
    const float* x  = (const float*)d_in[0];
    const float* Wq = (const float*)d_in[1];
    const float* bq = (const float*)d_in[2];
    const float* Wk = (const float*)d_in[3];
    const float* bk = (const float*)d_in[4];
    float* out = (float*)d_out;

    pool_att_kernel<<<NBC, 1024>>>(x, Wq, bq, Wk, bk);

    cudaLaunchAttribute attr[1];
    attr[0].id = cudaLaunchAttributeProgrammaticStreamSerialization;
    attr[0].val.programmaticStreamSerializationAllowed = 1;

    cudaLaunchConfig_t cfg = {};
    cfg.gridDim  = dim3(NCOL / 256);
    cfg.blockDim = dim3(256);
    cfg.dynamicSmemBytes = 0;
    cfg.stream = 0;
    cfg.attrs = attr;
    cfg.numAttrs = 1;
    cudaLaunchKernelEx(&cfg, av_kernel, x, out);
}